// round 1
// baseline (speedup 1.0000x reference)
#include <cuda_runtime.h>
#include <stdint.h>

// Problem: adjacency_full[i, neighbor_indices[i, j]] = adjacency_values[i, j]
// N = 8192, K = 64. Output: N*N fp32 (256 MB), zero-initialized then scattered.

#define N_PATCHES 8192
#define K_NEIGH   64

__global__ void scatter_kernel(const float* __restrict__ vals,
                               const int*   __restrict__ idx,
                               float* __restrict__ out)
{
    int t = blockIdx.x * blockDim.x + threadIdx.x;   // 0 .. N*K-1
    if (t >= N_PATCHES * K_NEIGH) return;
    int row = t >> 6;                // t / K
    int col = idx[t];                // coalesced read
    float v = vals[t];               // coalesced read
    out[(size_t)row * N_PATCHES + col] = v;  // scattered write (within row)
}

extern "C" void kernel_launch(void* const* d_in, const int* in_sizes, int n_in,
                              void* d_out, int out_size)
{
    const float* vals = (const float*)d_in[0];   // [N, K] float32
    const int*   idx  = (const int*)  d_in[1];   // [N, K] int32
    float* out = (float*)d_out;                  // [N, N] float32

    // 1) Zero-fill the 256 MB output (fastest possible: driver memset path).
    cudaMemsetAsync(out, 0, (size_t)out_size * sizeof(float), 0);

    // 2) Scatter the 512K sparse values.
    const int total = N_PATCHES * K_NEIGH;
    const int threads = 256;
    scatter_kernel<<<(total + threads - 1) / threads, threads, 0, 0>>>(vals, idx, out);
}

// round 2
// speedup vs baseline: 1.3300x; 1.3300x over previous
#include <cuda_runtime.h>
#include <stdint.h>

// adjacency_full[i, neighbor_indices[i, j]] = adjacency_values[i, j]
// N = 8192, K = 64. Output: N*N fp32 (256 MB).
//
// Fused single-pass kernel: one CTA per row. Build the final 32KB row in
// shared memory (zero + scatter 64 values), then stream it to GMEM with
// coalesced 128-bit stores. One pass over the 256MB output instead of
// memset-then-scatter (two passes, second one latency-bound).

#define N_PATCHES 8192
#define K_NEIGH   64
#define THREADS   256
#define ROW_VEC4  (N_PATCHES / 4)   // 2048 float4 per row

__global__ __launch_bounds__(THREADS)
void fused_row_kernel(const float* __restrict__ vals,
                      const int*   __restrict__ idx,
                      float* __restrict__ out)
{
    __shared__ float row[N_PATCHES];         // 32 KB
    const int r   = blockIdx.x;
    const int tid = threadIdx.x;

    // 1) Zero the row in shared memory (vectorized).
    float4* row4 = reinterpret_cast<float4*>(row);
    const float4 z4 = make_float4(0.f, 0.f, 0.f, 0.f);
    #pragma unroll
    for (int i = tid; i < ROW_VEC4; i += THREADS)
        row4[i] = z4;
    __syncthreads();

    // 2) Scatter this row's 64 values into shared memory.
    if (tid < K_NEIGH) {
        int t   = r * K_NEIGH + tid;
        int col = idx[t];        // coalesced (2 sectors per warp)
        row[col] = vals[t];      // smem scatter — cheap
    }
    __syncthreads();

    // 3) Stream the finished row to GMEM: fully coalesced 128-bit stores.
    float4* out4 = reinterpret_cast<float4*>(out + (size_t)r * N_PATCHES);
    #pragma unroll
    for (int i = tid; i < ROW_VEC4; i += THREADS)
        out4[i] = row4[i];
}

extern "C" void kernel_launch(void* const* d_in, const int* in_sizes, int n_in,
                              void* d_out, int out_size)
{
    const float* vals = (const float*)d_in[0];   // [N, K] float32
    const int*   idx  = (const int*)  d_in[1];   // [N, K] int32
    float* out = (float*)d_out;                  // [N, N] float32

    fused_row_kernel<<<N_PATCHES, THREADS, 0, 0>>>(vals, idx, out);
}